// round 2
// baseline (speedup 1.0000x reference)
#include <cuda_runtime.h>
#include <math.h>

#define Bn 8
#define Cn 64
#define On 64
#define Hn 128
#define Wn 128
#define HWn 16384
#define KKn 9

// scratch for sigmoid(mask conv): 8*9*128*128 floats = 4.7MB
__device__ float g_mask[Bn * KKn * HWn];

// ---------------------------------------------------------------------------
// Kernel A: fused 3x3 conv -> 18 offset channels (d_out offset region) and
// 9 mask channels (sigmoid -> g_mask). GEMM: block = one row (128 px) of one
// batch, oc padded to 32. 64 threads, tile 8px x 8oc. K=576 chunked by 72.
// ---------------------------------------------------------------------------
__global__ __launch_bounds__(64) void conv_offmask_kernel(
    const float* __restrict__ x,
    const float* __restrict__ p_w, const float* __restrict__ p_b,
    const float* __restrict__ m_w, const float* __restrict__ m_b,
    float* __restrict__ offs_out)
{
    __shared__ float sA[72 * 128];   // 36864 B
    __shared__ float sW[72 * 36];    // 10368 B
    const int h = blockIdx.x, b = blockIdx.y;
    const int tid = threadIdx.x;
    const int px4 = (tid & 15) * 4;        // pixels px4..px4+3 and +64
    const int ocg = (tid >> 4) * 8;        // 8 output channels
    const int row = h * Wn;

    float acc[8][8] = {};

    for (int c0 = 0; c0 < Cn; c0 += 8) {
        // im2col stage for this 8-channel chunk
        #pragma unroll 4
        for (int j = 0; j < 144; ++j) {
            int e = tid + j * 64;             // 0..9215
            int kk = e >> 7, i = e & 127;     // kk: c_local*9 + tap
            int c = c0 + kk / 9;
            int t = kk - (kk / 9) * 9;
            int y  = h - 1 + t / 3;
            int xc = i - 1 + (t - (t / 3) * 3);
            float v = 0.f;
            if ((unsigned)y < Hn && (unsigned)xc < Wn)
                v = x[(((size_t)(b * Cn + c)) << 14) + y * Wn + xc];
            sA[kk * 128 + i] = v;
        }
        // weight stage: 27 real oc + zero padding, [kk][o] layout
        for (int e = tid; e < 72 * 36; e += 64) {
            int o = e / 72, kk = e - o * 72;
            float v = 0.f;
            if (o < 18)      v = p_w[o * 576 + c0 * 9 + kk];
            else if (o < 27) v = m_w[(o - 18) * 576 + c0 * 9 + kk];
            sW[kk * 36 + o] = v;
        }
        __syncthreads();

        #pragma unroll 2
        for (int kk = 0; kk < 72; ++kk) {
            float4 aL = *(const float4*)&sA[kk * 128 + px4];
            float4 aH = *(const float4*)&sA[kk * 128 + px4 + 64];
            float4 w0 = *(const float4*)&sW[kk * 36 + ocg];
            float4 w1 = *(const float4*)&sW[kk * 36 + ocg + 4];
            float av[8] = {aL.x, aL.y, aL.z, aL.w, aH.x, aH.y, aH.z, aH.w};
            float wv[8] = {w0.x, w0.y, w0.z, w0.w, w1.x, w1.y, w1.z, w1.w};
            #pragma unroll
            for (int r = 0; r < 8; ++r)
                #pragma unroll
                for (int q = 0; q < 8; ++q)
                    acc[r][q] = fmaf(av[r], wv[q], acc[r][q]);
        }
        __syncthreads();
    }

    #pragma unroll
    for (int q = 0; q < 8; ++q) {
        int o = ocg + q;
        if (o < 18) {
            float bias = p_b[o];
            float* dst = offs_out + (((size_t)(b * 18 + o)) << 14) + row;
            #pragma unroll
            for (int r = 0; r < 4; ++r) dst[px4 + r]      = acc[r][q] + bias;
            #pragma unroll
            for (int r = 4; r < 8; ++r) dst[px4 + 60 + r] = acc[r][q] + bias;
        } else if (o < 27) {
            float bias = m_b[o - 18];
            float* dst = g_mask + (((size_t)(b * 9 + (o - 18))) << 14) + row;
            #pragma unroll
            for (int r = 0; r < 4; ++r) {
                float v = acc[r][q] + bias;
                dst[px4 + r] = 1.f / (1.f + expf(-v));
            }
            #pragma unroll
            for (int r = 4; r < 8; ++r) {
                float v = acc[r][q] + bias;
                dst[px4 + 60 + r] = 1.f / (1.f + expf(-v));
            }
        }
    }
}

// ---------------------------------------------------------------------------
// Kernel B: modulated deformable conv as tiled SGEMM.
// Block = one output row (128 px) x 64 oc of one batch. 128 threads
// (1 thread = 1 pixel for the gather), register tile 8px x 8oc.
// Bilinear corner indices/weights (mask+validity folded) precomputed once
// into smem, register-cached per tap during the gather (9 taps x 8 ch).
// ---------------------------------------------------------------------------
__global__ __launch_bounds__(128, 2) void deform_kernel(
    const float* __restrict__ x,
    const float* __restrict__ offs,
    const float* __restrict__ d_w, const float* __restrict__ d_b,
    float* __restrict__ out)
{
    extern __shared__ float smem[];
    float* sA = smem;                           // 72*128 = 36864 B
    float* sW = sA + 72 * 128;                  // 72*68  = 19584 B
    int4*   spos = (int4*)(sW + 72 * 68);       // 9*128*16 = 18432 B
    float4* swt  = (float4*)(spos + KKn * Wn);  // 9*128*16 = 18432 B

    const int h = blockIdx.x, b = blockIdx.y;
    const int tid = threadIdx.x;
    const int px4 = (tid & 15) * 4;
    const int ocg = (tid >> 4) * 8;
    const int row = h * Wn;

    // precompute bilinear corner indices + (mask*validity)-folded weights
    // thread tid owns pixel i = tid; 9 taps
    #pragma unroll
    for (int k = 0; k < KKn; ++k) {
        int i = tid;
        float dy = offs[(((size_t)(b * 18 + 2 * k)) << 14) + row + i];
        float dx = offs[(((size_t)(b * 18 + 2 * k + 1)) << 14) + row + i];
        float m  = g_mask[(((size_t)(b * 9 + k)) << 14) + row + i];
        int ki = k / 3, kj = k - ki * 3;
        float py = (float)(h - 1 + ki) + dy;
        float px = (float)(i - 1 + kj) + dx;
        float y0f = floorf(py), x0f = floorf(px);
        float fy = py - y0f, fx = px - x0f;
        int y0 = (int)y0f, x0 = (int)x0f;
        int y1 = y0 + 1, x1 = x0 + 1;
        float vy0 = ((unsigned)y0 < Hn) ? 1.f : 0.f;
        float vy1 = ((unsigned)y1 < Hn) ? 1.f : 0.f;
        float vx0 = ((unsigned)x0 < Wn) ? 1.f : 0.f;
        float vx1 = ((unsigned)x1 < Wn) ? 1.f : 0.f;
        float gy = 1.f - fy, gx = 1.f - fx;
        float4 wq;
        wq.x = gy * gx * m * vy0 * vx0;
        wq.y = gy * fx * m * vy0 * vx1;
        wq.z = fy * gx * m * vy1 * vx0;
        wq.w = fy * fx * m * vy1 * vx1;
        int cy0 = min(max(y0, 0), Hn - 1) * Wn;
        int cy1 = min(max(y1, 0), Hn - 1) * Wn;
        int cx0 = min(max(x0, 0), Wn - 1);
        int cx1 = min(max(x1, 0), Wn - 1);
        spos[k * 128 + i] = make_int4(cy0 + cx0, cy0 + cx1, cy1 + cx0, cy1 + cx1);
        swt[k * 128 + i]  = wq;
    }
    __syncthreads();

    float acc[8][8] = {};

    for (int c0 = 0; c0 < Cn; c0 += 8) {
        // weight stage first (independent LDGs overlap with gather)
        #pragma unroll
        for (int j = 0; j < 36; ++j) {
            int e = tid + j * 128;            // 0..4607
            int o = e / 72, kk = e - o * 72;
            sW[kk * 68 + o] = d_w[o * 576 + c0 * 9 + kk];
        }
        // gather stage: thread = pixel tid; per tap, pos/wt register-cached
        {
            const float* pl = x + (((size_t)(b * Cn + c0)) << 14);
            #pragma unroll 3
            for (int t = 0; t < KKn; ++t) {
                int4  p4 = spos[t * 128 + tid];
                float4 w4 = swt[t * 128 + tid];
                const float* p = pl;
                #pragma unroll
                for (int c = 0; c < 8; ++c) {
                    float v = w4.x * __ldg(p + p4.x)
                            + w4.y * __ldg(p + p4.y)
                            + w4.z * __ldg(p + p4.z)
                            + w4.w * __ldg(p + p4.w);
                    sA[(c * 9 + t) * 128 + tid] = v;
                    p += HWn;
                }
            }
        }
        __syncthreads();

        #pragma unroll 2
        for (int kk = 0; kk < 72; ++kk) {
            float4 aL = *(const float4*)&sA[kk * 128 + px4];
            float4 aH = *(const float4*)&sA[kk * 128 + px4 + 64];
            float4 w0 = *(const float4*)&sW[kk * 68 + ocg];
            float4 w1 = *(const float4*)&sW[kk * 68 + ocg + 4];
            float av[8] = {aL.x, aL.y, aL.z, aL.w, aH.x, aH.y, aH.z, aH.w};
            float wv[8] = {w0.x, w0.y, w0.z, w0.w, w1.x, w1.y, w1.z, w1.w};
            #pragma unroll
            for (int r = 0; r < 8; ++r)
                #pragma unroll
                for (int q = 0; q < 8; ++q)
                    acc[r][q] = fmaf(av[r], wv[q], acc[r][q]);
        }
        __syncthreads();
    }

    #pragma unroll
    for (int q = 0; q < 8; ++q) {
        int o = ocg + q;
        float bias = __ldg(d_b + o);
        float* dst = out + (((size_t)(b * On + o)) << 14) + row;
        float4 lo = make_float4(acc[0][q] + bias, acc[1][q] + bias,
                                acc[2][q] + bias, acc[3][q] + bias);
        float4 hi = make_float4(acc[4][q] + bias, acc[5][q] + bias,
                                acc[6][q] + bias, acc[7][q] + bias);
        *(float4*)&dst[px4]      = lo;
        *(float4*)&dst[px4 + 64] = hi;
    }
}

// ---------------------------------------------------------------------------

extern "C" void kernel_launch(void* const* d_in, const int* in_sizes, int n_in,
                              void* d_out, int out_size) {
    const float* x    = (const float*)d_in[0];
    const float* p_w  = (const float*)d_in[1];
    const float* p_b  = (const float*)d_in[2];
    const float* m_w  = (const float*)d_in[3];
    const float* m_b  = (const float*)d_in[4];
    const float* d_wp = (const float*)d_in[5];
    const float* d_bp = (const float*)d_in[6];

    float* out = (float*)d_out;                         // [8,64,128,128]
    float* offs_out = out + (size_t)Bn * On * HWn;      // [8,18,128,128]

    const int smemB = (72 * 128 + 72 * 68) * 4 + KKn * Wn * 16 * 2;  // 93312
    cudaFuncSetAttribute(deform_kernel,
                         cudaFuncAttributeMaxDynamicSharedMemorySize, smemB);

    dim3 grid(Hn, Bn);
    conv_offmask_kernel<<<grid, 64>>>(x, p_w, p_b, m_w, m_b, offs_out);
    deform_kernel<<<grid, 128, smemB>>>(x, offs_out, d_wp, d_bp, out);
}

// round 3
// speedup vs baseline: 1.2704x; 1.2704x over previous
#include <cuda_runtime.h>
#include <math.h>

#define Bn 8
#define Cn 64
#define On 64
#define Hn 128
#define Wn 128
#define HWn 16384
#define KKn 9

// scratch for sigmoid(mask conv): 8*9*128*128 floats = 4.7MB
__device__ float g_mask[Bn * KKn * HWn];

// ---------------------------------------------------------------------------
// Kernel A: fused 3x3 conv -> 18 offset channels + 9 mask channels (sigmoid).
// Block = one row (128px) of one batch, 256 threads, tile 4px x 4oc (32 padded
// oc). x staged as raw rows (3 x 132 per channel, zero-padded), weights staged
// once for all K. Window loads: float4+float2 serve all 3 horizontal taps.
// ---------------------------------------------------------------------------
__global__ __launch_bounds__(256) void conv_offmask_kernel(
    const float* __restrict__ x,
    const float* __restrict__ p_w, const float* __restrict__ p_b,
    const float* __restrict__ m_w, const float* __restrict__ m_b,
    float* __restrict__ offs_out)
{
    extern __shared__ float smemA[];
    float* sX = smemA;            // 8 * 3 * 132 = 3168 floats (12672 B)
    float* sW = smemA + 3168;     // 576 * 36    = 20736 floats (82944 B)

    const int h = blockIdx.x, b = blockIdx.y;
    const int tid = threadIdx.x;
    const int px4 = (tid & 31) * 4;      // 4 consecutive pixels
    const int ocg = (tid >> 5) * 4;      // 4 output channels (0..28)
    const int row = h * Wn;

    // stage all weights once: sW[kk][o], o padded to 36 (27 real)
    #pragma unroll 4
    for (int e = tid; e < 576 * 36; e += 256) {
        int o = e / 576, kk = e - o * 576;
        float v = 0.f;
        if (o < 18)      v = p_w[o * 576 + kk];
        else if (o < 27) v = m_w[(o - 18) * 576 + kk];
        sW[kk * 36 + o] = v;
    }

    float acc[4][4] = {};

    for (int c0 = 0; c0 < Cn; c0 += 8) {
        __syncthreads();   // protect sX reuse (and first-iter sW readiness)
        // stage 3 raw rows x 8 channels, width 132 (zero pad col 0, 129..131)
        for (int e = tid; e < 3168; e += 256) {
            int c = e / 396;
            int rem = e - c * 396;
            int r = rem / 132;
            int i = rem - r * 132;
            int y = h - 1 + r, xc = i - 1;
            float v = 0.f;
            if ((unsigned)y < Hn && (unsigned)xc < Wn)
                v = x[(((size_t)(b * Cn + c0 + c)) << 14) + y * Wn + xc];
            sX[e] = v;
        }
        __syncthreads();

        #pragma unroll
        for (int c = 0; c < 8; ++c) {
            #pragma unroll
            for (int ki = 0; ki < 3; ++ki) {
                const float* rowp = sX + c * 396 + ki * 132;
                float4 X0 = *(const float4*)&rowp[px4];
                float2 X1 = *(const float2*)&rowp[px4 + 4];
                float xs[6] = {X0.x, X0.y, X0.z, X0.w, X1.x, X1.y};
                int kkb = (c0 + c) * 9 + ki * 3;
                #pragma unroll
                for (int kj = 0; kj < 3; ++kj) {
                    float4 wv = *(const float4*)&sW[(kkb + kj) * 36 + ocg];
                    #pragma unroll
                    for (int r = 0; r < 4; ++r) {
                        float a = xs[r + kj];
                        acc[r][0] = fmaf(a, wv.x, acc[r][0]);
                        acc[r][1] = fmaf(a, wv.y, acc[r][1]);
                        acc[r][2] = fmaf(a, wv.z, acc[r][2]);
                        acc[r][3] = fmaf(a, wv.w, acc[r][3]);
                    }
                }
            }
        }
    }

    #pragma unroll
    for (int q = 0; q < 4; ++q) {
        int o = ocg + q;
        if (o < 18) {
            float bias = p_b[o];
            float* dst = offs_out + (((size_t)(b * 18 + o)) << 14) + row;
            float4 v = make_float4(acc[0][q] + bias, acc[1][q] + bias,
                                   acc[2][q] + bias, acc[3][q] + bias);
            *(float4*)&dst[px4] = v;
        } else if (o < 27) {
            float bias = m_b[o - 18];
            float* dst = g_mask + (((size_t)(b * 9 + (o - 18))) << 14) + row;
            float4 v;
            v.x = 1.f / (1.f + expf(-(acc[0][q] + bias)));
            v.y = 1.f / (1.f + expf(-(acc[1][q] + bias)));
            v.z = 1.f / (1.f + expf(-(acc[2][q] + bias)));
            v.w = 1.f / (1.f + expf(-(acc[3][q] + bias)));
            *(float4*)&dst[px4] = v;
        }
    }
}

// ---------------------------------------------------------------------------
// Kernel B: modulated deformable conv as tiled SGEMM.
// Block = one output row (128 px) x 64 oc of one batch, 256 threads.
// Thread tile 8px x 4oc (32 acc regs -> 2 blocks/SM, 16 warps).
// Bilinear corner offsets precomputed as short4 (fits: idx < 16384), weights
// with mask+validity folded as float4. Gather: thread = (pixel, 4-ch half).
// ---------------------------------------------------------------------------
__global__ __launch_bounds__(256, 2) void deform_kernel(
    const float* __restrict__ x,
    const float* __restrict__ offs,
    const float* __restrict__ d_w, const float* __restrict__ d_b,
    float* __restrict__ out)
{
    extern __shared__ float smem[];
    float* sA = smem;                           // 72*128 = 36864 B
    float* sW = sA + 72 * 128;                  // 72*68  = 19584 B
    short4* spos = (short4*)(sW + 72 * 68);     // 9*128*8  = 9216 B
    float4* swt  = (float4*)(spos + KKn * Wn);  // 9*128*16 = 18432 B

    const int h = blockIdx.x, b = blockIdx.y;
    const int tid = threadIdx.x;
    const int px4 = (tid & 15) * 4;             // pixels px4..+3 and +64..
    const int ocg = (tid >> 4) * 4;             // 4 output channels
    const int row = h * Wn;

    // precompute bilinear corner indices + (mask*validity)-folded weights
    for (int e = tid; e < KKn * Wn; e += 256) {
        int i = e & 127, k = e >> 7;
        float dy = offs[(((size_t)(b * 18 + 2 * k)) << 14) + row + i];
        float dx = offs[(((size_t)(b * 18 + 2 * k + 1)) << 14) + row + i];
        float m  = g_mask[(((size_t)(b * 9 + k)) << 14) + row + i];
        int ki = k / 3, kj = k - ki * 3;
        float py = (float)(h - 1 + ki) + dy;
        float px = (float)(i - 1 + kj) + dx;
        float y0f = floorf(py), x0f = floorf(px);
        float fy = py - y0f, fx = px - x0f;
        int y0 = (int)y0f, x0 = (int)x0f;
        int y1 = y0 + 1, x1 = x0 + 1;
        float vy0 = ((unsigned)y0 < Hn) ? 1.f : 0.f;
        float vy1 = ((unsigned)y1 < Hn) ? 1.f : 0.f;
        float vx0 = ((unsigned)x0 < Wn) ? 1.f : 0.f;
        float vx1 = ((unsigned)x1 < Wn) ? 1.f : 0.f;
        float gy = 1.f - fy, gx = 1.f - fx;
        float4 wq;
        wq.x = gy * gx * m * vy0 * vx0;
        wq.y = gy * fx * m * vy0 * vx1;
        wq.z = fy * gx * m * vy1 * vx0;
        wq.w = fy * fx * m * vy1 * vx1;
        int cy0 = min(max(y0, 0), Hn - 1) * Wn;
        int cy1 = min(max(y1, 0), Hn - 1) * Wn;
        int cx0 = min(max(x0, 0), Wn - 1);
        int cx1 = min(max(x1, 0), Wn - 1);
        short4 sp;
        sp.x = (short)(cy0 + cx0);
        sp.y = (short)(cy0 + cx1);
        sp.z = (short)(cy1 + cx0);
        sp.w = (short)(cy1 + cx1);
        spos[e] = sp;
        swt[e]  = wq;
    }

    float acc[8][4] = {};
    const int px_g  = tid & 127;        // gather: this thread's pixel
    const int half  = tid >> 7;         // gather: channel half (0/1 -> 4 ch)

    for (int c0 = 0; c0 < Cn; c0 += 8) {
        __syncthreads();   // prev GEMM done (also orders pos stage on iter 0)
        // weight stage first: independent LDGs in flight
        #pragma unroll
        for (int j = 0; j < 18; ++j) {
            int e = tid + j * 256;            // 0..4607
            int o = e / 72, kk = e - o * 72;
            sW[kk * 68 + o] = d_w[o * 576 + c0 * 9 + kk];
        }
        // gather: thread = (pixel, 4-channel half); per-tap regs cached
        {
            const float* pl = x + (((size_t)(b * Cn + c0 + half * 4)) << 14);
            #pragma unroll 3
            for (int t = 0; t < KKn; ++t) {
                short4 sp = spos[t * 128 + px_g];
                float4 w4 = swt[t * 128 + px_g];
                int p0 = sp.x, p1 = sp.y, p2 = sp.z, p3 = sp.w;
                const float* p = pl;
                #pragma unroll
                for (int c = 0; c < 4; ++c) {
                    float v = w4.x * __ldg(p + p0)
                            + w4.y * __ldg(p + p1)
                            + w4.z * __ldg(p + p2)
                            + w4.w * __ldg(p + p3);
                    sA[((half * 4 + c) * 9 + t) * 128 + px_g] = v;
                    p += HWn;
                }
            }
        }
        __syncthreads();

        #pragma unroll 4
        for (int kk = 0; kk < 72; ++kk) {
            const float* ap = sA + kk * 128;
            float4 aL = *(const float4*)&ap[px4];
            float4 aH = *(const float4*)&ap[px4 + 64];
            float4 wv = *(const float4*)&sW[kk * 68 + ocg];
            float av[8] = {aL.x, aL.y, aL.z, aL.w, aH.x, aH.y, aH.z, aH.w};
            #pragma unroll
            for (int r = 0; r < 8; ++r) {
                acc[r][0] = fmaf(av[r], wv.x, acc[r][0]);
                acc[r][1] = fmaf(av[r], wv.y, acc[r][1]);
                acc[r][2] = fmaf(av[r], wv.z, acc[r][2]);
                acc[r][3] = fmaf(av[r], wv.w, acc[r][3]);
            }
        }
    }

    #pragma unroll
    for (int q = 0; q < 4; ++q) {
        int o = ocg + q;
        float bias = __ldg(d_b + o);
        float* dst = out + (((size_t)(b * On + o)) << 14) + row;
        float4 lo = make_float4(acc[0][q] + bias, acc[1][q] + bias,
                                acc[2][q] + bias, acc[3][q] + bias);
        float4 hi = make_float4(acc[4][q] + bias, acc[5][q] + bias,
                                acc[6][q] + bias, acc[7][q] + bias);
        *(float4*)&dst[px4]      = lo;
        *(float4*)&dst[px4 + 64] = hi;
    }
}

// ---------------------------------------------------------------------------

extern "C" void kernel_launch(void* const* d_in, const int* in_sizes, int n_in,
                              void* d_out, int out_size) {
    const float* x    = (const float*)d_in[0];
    const float* p_w  = (const float*)d_in[1];
    const float* p_b  = (const float*)d_in[2];
    const float* m_w  = (const float*)d_in[3];
    const float* m_b  = (const float*)d_in[4];
    const float* d_wp = (const float*)d_in[5];
    const float* d_bp = (const float*)d_in[6];

    float* out = (float*)d_out;                         // [8,64,128,128]
    float* offs_out = out + (size_t)Bn * On * HWn;      // [8,18,128,128]

    const int smemA = (3168 + 576 * 36) * 4;                       // 95616
    const int smemB = (72 * 128 + 72 * 68) * 4 + KKn * Wn * (8 + 16); // 84096
    cudaFuncSetAttribute(conv_offmask_kernel,
                         cudaFuncAttributeMaxDynamicSharedMemorySize, smemA);
    cudaFuncSetAttribute(deform_kernel,
                         cudaFuncAttributeMaxDynamicSharedMemorySize, smemB);

    dim3 grid(Hn, Bn);
    conv_offmask_kernel<<<grid, 256, smemA>>>(x, p_w, p_b, m_w, m_b, offs_out);
    deform_kernel<<<grid, 256, smemB>>>(x, offs_out, d_wp, d_bp, out);
}

// round 4
// speedup vs baseline: 1.5025x; 1.1827x over previous
#include <cuda_runtime.h>
#include <math.h>

#define Bn 8
#define Cn 64
#define On 64
#define Hn 128
#define Wn 128
#define HWn 16384
#define KKn 9

// scratch for sigmoid(mask conv): 8*9*128*128 floats = 4.7MB
__device__ float g_mask[Bn * KKn * HWn];

// ---------------------------------------------------------------------------
// Kernel A: fused 3x3 conv -> 18 offset channels + 9 mask channels (sigmoid).
// Block = one row (128px) of one batch, 256 threads, tile 4px x 4oc.
// Balanced lane map: warp = 8 px-groups x 4 oc-groups (32px x 16oc) so the
// smem crossbar dedups both operands. Weights staged per 8-channel chunk
// (small static smem -> high occupancy). Window loads serve 3 horiz taps.
// ---------------------------------------------------------------------------
__global__ __launch_bounds__(256) void conv_offmask_kernel(
    const float* __restrict__ x,
    const float* __restrict__ p_w, const float* __restrict__ p_b,
    const float* __restrict__ m_w, const float* __restrict__ m_b,
    float* __restrict__ offs_out)
{
    __shared__ float sX[8 * 3 * 132];   // 12672 B
    __shared__ float sW[72 * 36];       // 10368 B

    const int h = blockIdx.x, b = blockIdx.y;
    const int tid = threadIdx.x;
    const int warp = tid >> 5, lane = tid & 31;
    const int px4 = ((warp & 3) * 8 + (lane & 7)) * 4;   // 4 pixels
    const int oc  = ((warp >> 2) * 4 + (lane >> 3)) * 4; // 4 out channels
    const int row = h * Wn;

    float acc[4][4] = {};

    for (int c0 = 0; c0 < Cn; c0 += 8) {
        __syncthreads();
        // stage 3 raw rows x 8 channels, width 132 (zero-pad halo)
        for (int e = tid; e < 3168; e += 256) {
            int c = e / 396;
            int rem = e - c * 396;
            int r = rem / 132;
            int i = rem - r * 132;
            int y = h - 1 + r, xc = i - 1;
            float v = 0.f;
            if ((unsigned)y < Hn && (unsigned)xc < Wn)
                v = x[(((size_t)(b * Cn + c0 + c)) << 14) + y * Wn + xc];
            sX[e] = v;
        }
        // stage weights for this chunk: sW[kk_local][o], o padded to 36
        #pragma unroll 2
        for (int e = tid; e < 72 * 36; e += 256) {
            int o = e / 72, kk = e - o * 72;
            float v = 0.f;
            if (o < 18)      v = p_w[o * 576 + c0 * 9 + kk];
            else if (o < 27) v = m_w[(o - 18) * 576 + c0 * 9 + kk];
            sW[kk * 36 + o] = v;
        }
        __syncthreads();

        #pragma unroll
        for (int c = 0; c < 8; ++c) {
            #pragma unroll
            for (int ki = 0; ki < 3; ++ki) {
                const float* rowp = sX + c * 396 + ki * 132;
                float4 X0 = *(const float4*)&rowp[px4];
                float2 X1 = *(const float2*)&rowp[px4 + 4];
                float xs[6] = {X0.x, X0.y, X0.z, X0.w, X1.x, X1.y};
                int kkb = c * 9 + ki * 3;
                #pragma unroll
                for (int kj = 0; kj < 3; ++kj) {
                    float4 wv = *(const float4*)&sW[(kkb + kj) * 36 + oc];
                    #pragma unroll
                    for (int r = 0; r < 4; ++r) {
                        float a = xs[r + kj];
                        acc[r][0] = fmaf(a, wv.x, acc[r][0]);
                        acc[r][1] = fmaf(a, wv.y, acc[r][1]);
                        acc[r][2] = fmaf(a, wv.z, acc[r][2]);
                        acc[r][3] = fmaf(a, wv.w, acc[r][3]);
                    }
                }
            }
        }
    }

    #pragma unroll
    for (int q = 0; q < 4; ++q) {
        int o = oc + q;
        if (o < 18) {
            float bias = p_b[o];
            float* dst = offs_out + (((size_t)(b * 18 + o)) << 14) + row;
            float4 v = make_float4(acc[0][q] + bias, acc[1][q] + bias,
                                   acc[2][q] + bias, acc[3][q] + bias);
            *(float4*)&dst[px4] = v;
        } else if (o < 27) {
            float bias = m_b[o - 18];
            float* dst = g_mask + (((size_t)(b * 9 + (o - 18))) << 14) + row;
            float4 v;
            v.x = 1.f / (1.f + expf(-(acc[0][q] + bias)));
            v.y = 1.f / (1.f + expf(-(acc[1][q] + bias)));
            v.z = 1.f / (1.f + expf(-(acc[2][q] + bias)));
            v.w = 1.f / (1.f + expf(-(acc[3][q] + bias)));
            *(float4*)&dst[px4] = v;
        }
    }
}

// ---------------------------------------------------------------------------
// Kernel B: modulated deformable conv as tiled SGEMM.
// Block = one output row (128 px) x 64 oc of one batch, 256 threads.
// Thread tile 4px x 8oc; balanced lane map: warp = 8 px-groups x 4 oc-groups
// (32px x 32oc) -> crossbar dedups A and W (128B each per kk per warp).
// Bilinear corners precomputed as short4 + folded weights. Gather: thread =
// (pixel, 4-ch half), per-tap pos/wt register-cached.
// ---------------------------------------------------------------------------
__global__ __launch_bounds__(256, 2) void deform_kernel(
    const float* __restrict__ x,
    const float* __restrict__ offs,
    const float* __restrict__ d_w, const float* __restrict__ d_b,
    float* __restrict__ out)
{
    extern __shared__ float smem[];
    float* sA = smem;                           // 72*128 = 36864 B
    float* sW = sA + 72 * 128;                  // 72*68  = 19584 B
    short4* spos = (short4*)(sW + 72 * 68);     // 9*128*8  = 9216 B
    float4* swt  = (float4*)(spos + KKn * Wn);  // 9*128*16 = 18432 B

    const int h = blockIdx.x, b = blockIdx.y;
    const int tid = threadIdx.x;
    const int warp = tid >> 5, lane = tid & 31;
    const int px4 = ((warp & 3) * 8 + (lane & 7)) * 4;   // 4 pixels
    const int oc8 = ((warp >> 2) * 4 + (lane >> 3)) * 8; // 8 out channels
    const int row = h * Wn;

    // precompute bilinear corner indices + (mask*validity)-folded weights
    for (int e = tid; e < KKn * Wn; e += 256) {
        int i = e & 127, k = e >> 7;
        float dy = offs[(((size_t)(b * 18 + 2 * k)) << 14) + row + i];
        float dx = offs[(((size_t)(b * 18 + 2 * k + 1)) << 14) + row + i];
        float m  = g_mask[(((size_t)(b * 9 + k)) << 14) + row + i];
        int ki = k / 3, kj = k - ki * 3;
        float py = (float)(h - 1 + ki) + dy;
        float px = (float)(i - 1 + kj) + dx;
        float y0f = floorf(py), x0f = floorf(px);
        float fy = py - y0f, fx = px - x0f;
        int y0 = (int)y0f, x0 = (int)x0f;
        int y1 = y0 + 1, x1 = x0 + 1;
        float vy0 = ((unsigned)y0 < Hn) ? 1.f : 0.f;
        float vy1 = ((unsigned)y1 < Hn) ? 1.f : 0.f;
        float vx0 = ((unsigned)x0 < Wn) ? 1.f : 0.f;
        float vx1 = ((unsigned)x1 < Wn) ? 1.f : 0.f;
        float gy = 1.f - fy, gx = 1.f - fx;
        float4 wq;
        wq.x = gy * gx * m * vy0 * vx0;
        wq.y = gy * fx * m * vy0 * vx1;
        wq.z = fy * gx * m * vy1 * vx0;
        wq.w = fy * fx * m * vy1 * vx1;
        int cy0 = min(max(y0, 0), Hn - 1) * Wn;
        int cy1 = min(max(y1, 0), Hn - 1) * Wn;
        int cx0 = min(max(x0, 0), Wn - 1);
        int cx1 = min(max(x1, 0), Wn - 1);
        short4 sp;
        sp.x = (short)(cy0 + cx0);
        sp.y = (short)(cy0 + cx1);
        sp.z = (short)(cy1 + cx0);
        sp.w = (short)(cy1 + cx1);
        spos[e] = sp;
        swt[e]  = wq;
    }

    float acc[4][8] = {};
    const int px_g  = tid & 127;        // gather: this thread's pixel
    const int half  = tid >> 7;         // gather: channel half (0/1 -> 4 ch)

    for (int c0 = 0; c0 < Cn; c0 += 8) {
        __syncthreads();   // prev GEMM done (also orders pos stage on iter 0)
        // weight stage first: independent LDGs in flight
        #pragma unroll
        for (int j = 0; j < 18; ++j) {
            int e = tid + j * 256;            // 0..4607
            int o = e / 72, kk = e - o * 72;
            sW[kk * 68 + o] = d_w[o * 576 + c0 * 9 + kk];
        }
        // gather: thread = (pixel, 4-channel half); per-tap regs cached
        {
            const float* pl = x + (((size_t)(b * Cn + c0 + half * 4)) << 14);
            #pragma unroll 3
            for (int t = 0; t < KKn; ++t) {
                short4 sp = spos[t * 128 + px_g];
                float4 w4 = swt[t * 128 + px_g];
                int p0 = sp.x, p1 = sp.y, p2 = sp.z, p3 = sp.w;
                const float* p = pl;
                #pragma unroll
                for (int c = 0; c < 4; ++c) {
                    float v = w4.x * __ldg(p + p0)
                            + w4.y * __ldg(p + p1)
                            + w4.z * __ldg(p + p2)
                            + w4.w * __ldg(p + p3);
                    sA[((half * 4 + c) * 9 + t) * 128 + px_g] = v;
                    p += HWn;
                }
            }
        }
        __syncthreads();

        #pragma unroll 4
        for (int kk = 0; kk < 72; ++kk) {
            float4 av = *(const float4*)&sA[kk * 128 + px4];
            float4 w0 = *(const float4*)&sW[kk * 68 + oc8];
            float4 w1 = *(const float4*)&sW[kk * 68 + oc8 + 4];
            float wv[8] = {w0.x, w0.y, w0.z, w0.w, w1.x, w1.y, w1.z, w1.w};
            float ar[4] = {av.x, av.y, av.z, av.w};
            #pragma unroll
            for (int r = 0; r < 4; ++r)
                #pragma unroll
                for (int q = 0; q < 8; ++q)
                    acc[r][q] = fmaf(ar[r], wv[q], acc[r][q]);
        }
    }

    #pragma unroll
    for (int q = 0; q < 8; ++q) {
        int o = oc8 + q;
        float bias = __ldg(d_b + o);
        float* dst = out + (((size_t)(b * On + o)) << 14) + row;
        float4 v = make_float4(acc[0][q] + bias, acc[1][q] + bias,
                               acc[2][q] + bias, acc[3][q] + bias);
        *(float4*)&dst[px4] = v;
    }
}

// ---------------------------------------------------------------------------

extern "C" void kernel_launch(void* const* d_in, const int* in_sizes, int n_in,
                              void* d_out, int out_size) {
    const float* x    = (const float*)d_in[0];
    const float* p_w  = (const float*)d_in[1];
    const float* p_b  = (const float*)d_in[2];
    const float* m_w  = (const float*)d_in[3];
    const float* m_b  = (const float*)d_in[4];
    const float* d_wp = (const float*)d_in[5];
    const float* d_bp = (const float*)d_in[6];

    float* out = (float*)d_out;                         // [8,64,128,128]
    float* offs_out = out + (size_t)Bn * On * HWn;      // [8,18,128,128]

    const int smemB = (72 * 128 + 72 * 68) * 4 + KKn * Wn * (8 + 16); // 84096
    cudaFuncSetAttribute(deform_kernel,
                         cudaFuncAttributeMaxDynamicSharedMemorySize, smemB);

    dim3 grid(Hn, Bn);
    conv_offmask_kernel<<<grid, 256>>>(x, p_w, p_b, m_w, m_b, offs_out);
    deform_kernel<<<grid, 256, smemB>>>(x, offs_out, d_wp, d_bp, out);
}